// round 6
// baseline (speedup 1.0000x reference)
#include <cuda_runtime.h>
#include <cuda_bf16.h>
#include <cstdint>

// INT4 symmetric grouped dequant — 256-bit ld/st, MLP=2 front-batch.
//   packed: TOTAL/2 int32 (one byte each, two nibbles: low = even elem, high = odd)
//   scale:  (4096, 86) fp32, group size 128
//   out:    fp32, out[i] = (nibble - 8) * scale[i/128]
//
// Each thread: TWO block-strided 32B v8 loads (front-batched -> MLP 2,
// each load fully coalesced 1KB/warp), then per tile 16 converts + two
// 32B v8 stores. 16 codes per v8 -> group = v8_index >> 3.
// oe*MLP_p1 = 8*2 = 16 = L1tex queue threshold: max safe intra-thread MLP.

#define N_PACKED   22544384              // TOTAL/2 int32s
#define N_V8       (N_PACKED / 8)        // 2,818,048 v8 tiles
#define THREADS    256
#define TILES      2
#define BLOCKS     (N_V8 / (THREADS * TILES))   // 5504 exact

__global__ void __launch_bounds__(THREADS)
int4_dequant_kernel(const uint32_t* __restrict__ packed,
                    const float* __restrict__ scale,
                    float* __restrict__ out)
{
    const int base = blockIdx.x * (THREADS * TILES) + threadIdx.x;  // v8 index

    // Front-batched independent 256-bit loads (MLP_p1 = 2)
    uint32_t p[TILES][8];
#pragma unroll
    for (int k = 0; k < TILES; ++k) {
        const uint32_t* src = packed + 8 * (size_t)(base + k * THREADS);
        asm volatile(
            "ld.global.cs.v8.b32 {%0,%1,%2,%3,%4,%5,%6,%7}, [%8];"
            : "=r"(p[k][0]), "=r"(p[k][1]), "=r"(p[k][2]), "=r"(p[k][3]),
              "=r"(p[k][4]), "=r"(p[k][5]), "=r"(p[k][6]), "=r"(p[k][7])
            : "l"(src));
    }

#pragma unroll
    for (int k = 0; k < TILES; ++k) {
        const int i = base + k * THREADS;            // v8 tile index
        const float s = __ldg(&scale[i >> 3]);       // cached, 128x reuse

        float f[16];
#pragma unroll
        for (int j = 0; j < 8; ++j) {
            f[2 * j]     = (float)((int)( p[k][j]       & 15u) - 8) * s;
            f[2 * j + 1] = (float)((int)((p[k][j] >> 4) & 15u) - 8) * s;
        }

        float* o = out + 16 * (size_t)i;
        asm volatile(
            "st.global.cs.v8.f32 [%0], {%1,%2,%3,%4,%5,%6,%7,%8};"
            :: "l"(o),
               "f"(f[0]), "f"(f[1]), "f"(f[2]), "f"(f[3]),
               "f"(f[4]), "f"(f[5]), "f"(f[6]), "f"(f[7])
            : "memory");
        asm volatile(
            "st.global.cs.v8.f32 [%0], {%1,%2,%3,%4,%5,%6,%7,%8};"
            :: "l"(o + 8),
               "f"(f[8]),  "f"(f[9]),  "f"(f[10]), "f"(f[11]),
               "f"(f[12]), "f"(f[13]), "f"(f[14]), "f"(f[15])
            : "memory");
    }
}

extern "C" void kernel_launch(void* const* d_in, const int* in_sizes, int n_in,
                              void* d_out, int out_size)
{
    const uint32_t* packed = (const uint32_t*)d_in[0];
    const float*    scale  = (const float*)d_in[1];
    float*          out    = (float*)d_out;

    int4_dequant_kernel<<<BLOCKS, THREADS>>>(packed, scale, out);
}